// round 7
// baseline (speedup 1.0000x reference)
#include <cuda_runtime.h>
#include <cstdint>

#define E 256
#define SLEN 64
#define TLEN 512
#define NB 128
#define CLU 8
#define NTHR 512

typedef unsigned long long u64;

// WA: [k=256][1024 cols]. Rank r owns cols [128r,128r+128):
//   c<32: W_w row (32r+c)  (v, scattered to batch owner)
//   c>=32: cc=c-32=3j+g: w_hh row (g*256+32r+j)  (gh triplets, kept local)
// WX: [k=512][1024]. c<96: 3j+g -> w_ih row (g*256+32r+j); c>=96: zero pad.
__device__ float4 g_WA[256 * 256];
__device__ float4 g_WX[512 * 256];

__global__ void prep(const float* __restrict__ Ww, const float* __restrict__ wih,
                     const float* __restrict__ whh) {
    int idx = blockIdx.x * blockDim.x + threadIdx.x;
    float* WA = (float*)g_WA;
    float* WX = (float*)g_WX;
    if (idx < 256 * 1024) {
        int k = idx >> 10, cg = idx & 1023, r = cg >> 7, c = cg & 127;
        if (c < 32) WA[idx] = Ww[(32 * r + c) * 256 + k];
        else {
            int cc = c - 32, j = cc / 3, g = cc - 3 * j;
            WA[idx] = whh[(g * 256 + 32 * r + j) * 256 + k];
        }
    }
    int idx2 = idx - 256 * 1024;
    if (idx2 >= 0 && idx2 < 512 * 1024) {
        int k = idx2 >> 10, cg = idx2 & 1023, r = cg >> 7, c = cg & 127;
        if (c < 96) {
            int j = c / 3, g = c - 3 * j;
            WX[idx2] = wih[(g * 256 + 32 * r + j) * 512 + k];
        } else WX[idx2] = 0.f;
    }
}

// ---------------- f32x2 helpers ---------------------------------------------
__device__ __forceinline__ u64 f2x2(float a, float b) {
    u64 r; asm("mov.b64 %0,{%1,%2};" : "=l"(r) : "f"(a), "f"(b)); return r;
}
__device__ __forceinline__ void unpk(u64 v, float& a, float& b) {
    asm("mov.b64 {%0,%1},%2;" : "=f"(a), "=f"(b) : "l"(v));
}
__device__ __forceinline__ u64 fma2(u64 a, u64 b, u64 c) {
    u64 d; asm("fma.rn.f32x2 %0,%1,%2,%3;" : "=l"(d) : "l"(a), "l"(b), "l"(c)); return d;
}
__device__ __forceinline__ u64 mul2(u64 a, u64 b) {
    u64 d; asm("mul.rn.f32x2 %0,%1,%2;" : "=l"(d) : "l"(a), "l"(b)); return d;
}
__device__ __forceinline__ u64 add2(u64 a, u64 b) {
    u64 d; asm("add.rn.f32x2 %0,%1,%2;" : "=l"(d) : "l"(a), "l"(b)); return d;
}
__device__ __forceinline__ uint32_t s2u(const void* p) {
    return (uint32_t)__cvta_generic_to_shared(p);
}
__device__ __forceinline__ void stc64(uint32_t a, uint32_t rk, u64 v) {
    uint32_t ra;
    asm volatile("mapa.shared::cluster.u32 %0,%1,%2;" : "=r"(ra) : "r"(a), "r"(rk));
    asm volatile("st.shared::cluster.u64 [%0],%1;" ::"r"(ra), "l"(v) : "memory");
}
__device__ __forceinline__ void carrive() {
    asm volatile("barrier.cluster.arrive.aligned;" ::: "memory");
}
__device__ __forceinline__ void cwait() {
    asm volatile("barrier.cluster.wait.aligned;" ::: "memory");
}

struct __align__(16) SM {
    u64 hdup[256 * 8];      // (h,h) per [k][bb]
    u64 lndup[512 * 8];     // (y,y) per [k][bb]
    float part[16 * 1026];  // matvec partials; reused as attention ctx scratch
    float v_own[E];
    float ctx_s[E];
    float gh_loc[8 * 96];
    float gx_loc[8 * 96];
    uint32_t msk[TLEN];
    float2 mS[16];
    float wgtS[16];
    float sgS;
    float redA[20];
    float redB[20];
};

template <int NT>
__device__ __forceinline__ void prefw(const ulonglong2* __restrict__ Wq,
                                      int lane, int warp, int rank,
                                      ulonglong2& p0, ulonglong2& p1,
                                      ulonglong2& p2, ulonglong2& p3) {
    const ulonglong2* wp = Wq + (size_t)(warp * NT * 4) * 256 + rank * 32 + lane;
    p0 = wp[0]; p1 = wp[256]; p2 = wp[512]; p3 = wp[768];
}

// 128-col slice (this rank) x 8 batches; warp = k-partition of NT*4.
// First weight tile arrives preloaded in w0..w3 (software pipeline).
template <int NT>
__device__ __forceinline__ void matslice2(const ulonglong2* __restrict__ Wq,
                                          const ulonglong2* __restrict__ hq,
                                          float* part, int lane, int warp, int rank,
                                          ulonglong2 w0, ulonglong2 w1,
                                          ulonglong2 w2, ulonglong2 w3) {
    u64 acc[2][8];
#pragma unroll
    for (int p = 0; p < 2; p++)
#pragma unroll
        for (int b = 0; b < 8; b++) acc[p][b] = 0ull;
    const ulonglong2* wp = Wq + (size_t)(warp * NT * 4) * 256 + rank * 32 + lane + 1024;
    const ulonglong2* hp = hq + (warp * NT * 4) * 4;
#pragma unroll 2
    for (int t = 0; t < NT; t++) {
        ulonglong2 n0 = w0, n1 = w1, n2 = w2, n3 = w3;
        if (t + 1 < NT) { n0 = wp[0]; n1 = wp[256]; n2 = wp[512]; n3 = wp[768]; wp += 1024; }
#pragma unroll
        for (int bp = 0; bp < 4; bp++) {
            ulonglong2 h0 = hp[bp], h1 = hp[4 + bp], h2 = hp[8 + bp], h3 = hp[12 + bp];
            int b0 = 2 * bp, b1 = 2 * bp + 1;
            acc[0][b0] = fma2(w0.x, h0.x, acc[0][b0]); acc[1][b0] = fma2(w0.y, h0.x, acc[1][b0]);
            acc[0][b1] = fma2(w0.x, h0.y, acc[0][b1]); acc[1][b1] = fma2(w0.y, h0.y, acc[1][b1]);
            acc[0][b0] = fma2(w1.x, h1.x, acc[0][b0]); acc[1][b0] = fma2(w1.y, h1.x, acc[1][b0]);
            acc[0][b1] = fma2(w1.x, h1.y, acc[0][b1]); acc[1][b1] = fma2(w1.y, h1.y, acc[1][b1]);
            acc[0][b0] = fma2(w2.x, h2.x, acc[0][b0]); acc[1][b0] = fma2(w2.y, h2.x, acc[1][b0]);
            acc[0][b1] = fma2(w2.x, h2.y, acc[0][b1]); acc[1][b1] = fma2(w2.y, h2.y, acc[1][b1]);
            acc[0][b0] = fma2(w3.x, h3.x, acc[0][b0]); acc[1][b0] = fma2(w3.y, h3.x, acc[1][b0]);
            acc[0][b1] = fma2(w3.x, h3.y, acc[0][b1]); acc[1][b1] = fma2(w3.y, h3.y, acc[1][b1]);
        }
        hp += 16;
        w0 = n0; w1 = n1; w2 = n2; w3 = n3;
    }
#pragma unroll
    for (int p = 0; p < 2; p++)
#pragma unroll
        for (int b = 0; b < 8; b++) {
            int x = b * 128 + 4 * lane + 2 * p;
            *(u64*)(part + warp * 1026 + x) = acc[p][b];
        }
}

__device__ __forceinline__ void mat_reduce(SM* sm, int tid, int rank, int phase) {
    int x = 2 * tid;
    u64 s = 0ull;
#pragma unroll
    for (int w = 0; w < 16; w++) s = add2(s, *(const u64*)(sm->part + w * 1026 + x));
    int bb = x >> 7, c = x & 127;
    if (phase == 0) {
        if (c < 32) {
            if (bb == rank) *(u64*)(&sm->v_own[32 * rank + c]) = s;
            else stc64(s2u(&sm->v_own[32 * rank + c]), (uint32_t)bb, s);
        } else *(u64*)(&sm->gh_loc[bb * 96 + (c - 32)]) = s;
    } else {
        if (c < 96) *(u64*)(&sm->gx_loc[bb * 96 + c]) = s;
    }
}

__global__ void __cluster_dims__(CLU, 1, 1) __launch_bounds__(NTHR, 1)
gru(const float* __restrict__ sig, const float* __restrict__ bases,
    const uint32_t* __restrict__ mask, const float* __restrict__ Wb,
    const float* __restrict__ lng, const float* __restrict__ lnb,
    const float* __restrict__ bih, const float* __restrict__ bhh,
    const float* __restrict__ h0, float* __restrict__ out) {
    extern __shared__ char smraw[];
    SM* sm = (SM*)smraw;
    const int tid = threadIdx.x, lane = tid & 31, warp = tid >> 5;
    const int b = blockIdx.x;
    uint32_t rank;
    asm("mov.u32 %0,%%cluster_ctarank;" : "=r"(rank));
    const float NEGINF = __int_as_float(0xff800000);

    // per-thread constants
    float bihr = 0.f, bihz = 0.f, bihn = 0.f;
    float bhhr = 0.f, bhhz = 0.f, bhhn = 0.f, hreg = 0.f;
    const int gj = tid & 31, gbb = tid >> 5;  // gate mapping for tid<256
    if (tid < 256) {
        int i = 32 * rank + gj;
        bihr = bih[i]; bihz = bih[256 + i]; bihn = bih[512 + i];
        bhhr = bhh[i]; bhhz = bhh[256 + i]; bhhn = bhh[512 + i];
        hreg = h0[i];
        u64 hv = f2x2(h0[tid], h0[tid]);
#pragma unroll
        for (int bb = 0; bb < 8; bb++) sm->hdup[tid * 8 + bb] = hv;
    }
    const float lngr = lng[tid], lnbr = lnb[tid];
    // attention bias, folded per-lane (v_own stays raw)
    const ulonglong2 wbA = ((const ulonglong2*)Wb)[2 * lane];
    const ulonglong2 wbB = ((const ulonglong2*)Wb)[2 * lane + 1];
    for (int t = tid; t < TLEN; t += NTHR) sm->msk[t] = mask[(size_t)b * TLEN + t];
    __syncthreads();
    carrive(); cwait();

    const ulonglong2* sq = (const ulonglong2*)(sig + (size_t)b * TLEN * E);
    const int b_base = b & ~7;

    ulonglong2 pA0, pA1, pA2, pA3;
    prefw<4>((const ulonglong2*)g_WA, lane, warp, rank, pA0, pA1, pA2, pA3);

    for (int s = 0; s < SLEN; s++) {
        float xbase = 0.f;
        if (tid < 256) xbase = bases[((size_t)b * SLEN + s) * E + tid];

        // ===== Phase A: v (scatter to owner) + gh (local), all 8 batches ====
        matslice2<4>((const ulonglong2*)g_WA, (const ulonglong2*)sm->hdup,
                     sm->part, lane, warp, rank, pA0, pA1, pA2, pA3);
        __syncthreads();
        mat_reduce(sm, tid, rank, 0);
        carrive();
        // prefetch attention group 0 signal while the cluster barrier drains
        const int t0 = warp * 32;
        ulonglong2 P0 = sq[(size_t)(t0 + 0) * 64 + 2 * lane];
        ulonglong2 P1 = sq[(size_t)(t0 + 0) * 64 + 2 * lane + 1];
        ulonglong2 P2 = sq[(size_t)(t0 + 1) * 64 + 2 * lane];
        ulonglong2 P3 = sq[(size_t)(t0 + 1) * 64 + 2 * lane + 1];
        ulonglong2 P4 = sq[(size_t)(t0 + 2) * 64 + 2 * lane];
        ulonglong2 P5 = sq[(size_t)(t0 + 2) * 64 + 2 * lane + 1];
        ulonglong2 P6 = sq[(size_t)(t0 + 3) * 64 + 2 * lane];
        ulonglong2 P7 = sq[(size_t)(t0 + 3) * 64 + 2 * lane + 1];
        cwait();

        // ===== Attention (own batch), 32 t per warp, groups of 4 ============
        ulonglong2 vr0 = ((const ulonglong2*)sm->v_own)[2 * lane];
        ulonglong2 vr1 = ((const ulonglong2*)sm->v_own)[2 * lane + 1];
        ulonglong2 va, vb;
        va.x = add2(vr0.x, wbA.x); va.y = add2(vr0.y, wbA.y);
        vb.x = add2(vr1.x, wbB.x); vb.y = add2(vr1.y, wbB.y);
        float mrun = -1e30f, Ss = 0.f;
        u64 c0 = 0, c1 = 0, c2 = 0, c3 = 0;

        auto att_group = [&](int tg, ulonglong2 r0a, ulonglong2 r0b, ulonglong2 r1a,
                             ulonglong2 r1b, ulonglong2 r2a, ulonglong2 r2b,
                             ulonglong2 r3a, ulonglong2 r3b) {
            auto dotp = [&](ulonglong2 ra, ulonglong2 rb) {
                u64 a = mul2(ra.x, va.x);
                a = fma2(ra.y, va.y, a);
                a = fma2(rb.x, vb.x, a);
                a = fma2(rb.y, vb.y, a);
                float lo, hi; unpk(a, lo, hi);
                return lo + hi;
            };
            float a0 = dotp(r0a, r0b), a1 = dotp(r1a, r1b);
            float a2 = dotp(r2a, r2b), a3 = dotp(r3a, r3b);
#pragma unroll
            for (int o = 16; o; o >>= 1) {
                a0 += __shfl_xor_sync(0xffffffffu, a0, o);
                a1 += __shfl_xor_sync(0xffffffffu, a1, o);
                a2 += __shfl_xor_sync(0xffffffffu, a2, o);
                a3 += __shfl_xor_sync(0xffffffffu, a3, o);
            }
            if (sm->msk[tg + 0]) a0 = NEGINF;
            if (sm->msk[tg + 1]) a1 = NEGINF;
            if (sm->msk[tg + 2]) a2 = NEGINF;
            if (sm->msk[tg + 3]) a3 = NEGINF;
            float mg = fmaxf(fmaxf(a0, a1), fmaxf(a2, a3));
            if (mg > mrun) {
                float sc = __expf(mrun - mg);
                mrun = mg; Ss *= sc;
                u64 sc2 = f2x2(sc, sc);
                c0 = mul2(c0, sc2); c1 = mul2(c1, sc2);
                c2 = mul2(c2, sc2); c3 = mul2(c3, sc2);
            }
            float p0 = __expf(a0 - mrun), p1 = __expf(a1 - mrun);
            float p2 = __expf(a2 - mrun), p3 = __expf(a3 - mrun);
            Ss += (p0 + p1) + (p2 + p3);
            u64 q0 = f2x2(p0, p0), q1 = f2x2(p1, p1), q2 = f2x2(p2, p2), q3 = f2x2(p3, p3);
            c0 = fma2(q0, r0a.x, c0); c1 = fma2(q0, r0a.y, c1);
            c2 = fma2(q0, r0b.x, c2); c3 = fma2(q0, r0b.y, c3);
            c0 = fma2(q1, r1a.x, c0); c1 = fma2(q1, r1a.y, c1);
            c2 = fma2(q1, r1b.x, c2); c3 = fma2(q1, r1b.y, c3);
            c0 = fma2(q2, r2a.x, c0); c1 = fma2(q2, r2a.y, c1);
            c2 = fma2(q2, r2b.x, c2); c3 = fma2(q2, r2b.y, c3);
            c0 = fma2(q3, r3a.x, c0); c1 = fma2(q3, r3a.y, c1);
            c2 = fma2(q3, r3b.x, c2); c3 = fma2(q3, r3b.y, c3);
        };

        att_group(t0, P0, P1, P2, P3, P4, P5, P6, P7);
#pragma unroll 2
        for (int g = 1; g < 8; g++) {
            int tg = t0 + g * 4;
            ulonglong2 r0a = sq[(size_t)(tg + 0) * 64 + 2 * lane];
            ulonglong2 r0b = sq[(size_t)(tg + 0) * 64 + 2 * lane + 1];
            ulonglong2 r1a = sq[(size_t)(tg + 1) * 64 + 2 * lane];
            ulonglong2 r1b = sq[(size_t)(tg + 1) * 64 + 2 * lane + 1];
            ulonglong2 r2a = sq[(size_t)(tg + 2) * 64 + 2 * lane];
            ulonglong2 r2b = sq[(size_t)(tg + 2) * 64 + 2 * lane + 1];
            ulonglong2 r3a = sq[(size_t)(tg + 3) * 64 + 2 * lane];
            ulonglong2 r3b = sq[(size_t)(tg + 3) * 64 + 2 * lane + 1];
            att_group(tg, r0a, r0b, r1a, r1b, r2a, r2b, r3a, r3b);
        }
        {
            u64* cw = (u64*)sm->part + warp * 132 + lane * 4;
            cw[0] = c0; cw[1] = c1; cw[2] = c2; cw[3] = c3;
            if (lane == 0) sm->mS[warp] = make_float2(mrun, Ss);
        }
        __syncthreads();
        if (tid < 32) {
            float mw = (lane < 16) ? sm->mS[lane].x : NEGINF;
            float Sw = (lane < 16) ? sm->mS[lane].y : 0.f;
            float m = mw;
#pragma unroll
            for (int o = 16; o; o >>= 1) m = fmaxf(m, __shfl_xor_sync(0xffffffffu, m, o));
            float wgt = __expf(mw - m);
            float Sc = Sw * wgt;
#pragma unroll
            for (int o = 16; o; o >>= 1) Sc += __shfl_xor_sync(0xffffffffu, Sc, o);
            if (lane < 16) sm->wgtS[lane] = wgt;
            if (lane == 0) sm->sgS = Sc;
        }
        __syncthreads();
        if (tid < 256) {
            float acc = 0.f;
#pragma unroll
            for (int w = 0; w < 16; w++) acc += sm->part[w * 264 + tid] * sm->wgtS[w];
            sm->ctx_s[tid] = acc / sm->sgS;
        }
        __syncthreads();

        // ===== LayerNorm over [x, ctx] and broadcast (y,y) to cluster =======
        float xv = (tid < 256) ? xbase : sm->ctx_s[tid - 256];
        ulonglong2 pC0, pC1, pC2, pC3;
        {
            float s1 = xv, s2 = xv * xv;
#pragma unroll
            for (int o = 16; o; o >>= 1) {
                s1 += __shfl_xor_sync(0xffffffffu, s1, o);
                s2 += __shfl_xor_sync(0xffffffffu, s2, o);
            }
            if (lane == 0) { sm->redA[warp] = s1; sm->redB[warp] = s2; }
            __syncthreads();
            if (tid < 32) {
                float x1 = (lane < 16) ? sm->redA[lane] : 0.f;
                float x2 = (lane < 16) ? sm->redB[lane] : 0.f;
#pragma unroll
                for (int o = 16; o; o >>= 1) {
                    x1 += __shfl_xor_sync(0xffffffffu, x1, o);
                    x2 += __shfl_xor_sync(0xffffffffu, x2, o);
                }
                if (lane == 0) { sm->redA[16] = x1; sm->redB[16] = x2; }
            }
            __syncthreads();
            float mu = sm->redA[16] * (1.f / 512.f);
            float var = sm->redB[16] * (1.f / 512.f) - mu * mu;
            float rstd = rsqrtf(var + 1e-5f);
            float y = (xv - mu) * rstd * lngr + lnbr;
            u64 y2 = f2x2(y, y);
            sm->lndup[tid * 8 + rank] = y2;  // own rank local
            uint32_t addr = s2u(&sm->lndup[tid * 8 + rank]);
#pragma unroll
            for (uint32_t rr = 0; rr < CLU; rr++)
                if (rr != rank) stc64(addr, rr, y2);
        }
        carrive();
        prefw<8>((const ulonglong2*)g_WX, lane, warp, rank, pC0, pC1, pC2, pC3);
        cwait();

        // ===== Phase C: gx (local triplets), all 8 batches ==================
        matslice2<8>((const ulonglong2*)g_WX, (const ulonglong2*)sm->lndup,
                     sm->part, lane, warp, rank, pC0, pC1, pC2, pC3);
        __syncthreads();
        mat_reduce(sm, tid, rank, 1);
        __syncthreads();

        // ===== Gates for this rank's 32 h-indices, all 8 batches ============
        if (tid < 256) {
            int base = gbb * 96 + 3 * gj;
            float gxr = sm->gx_loc[base], gxz = sm->gx_loc[base + 1], gxn = sm->gx_loc[base + 2];
            float ghr = sm->gh_loc[base], ghz = sm->gh_loc[base + 1], ghn = sm->gh_loc[base + 2];
            float r = 1.f / (1.f + __expf(-(gxr + bihr + ghr + bhhr)));
            float z = 1.f / (1.f + __expf(-(gxz + bihz + ghz + bhhz)));
            float n = tanhf(gxn + bihn + r * (ghn + bhhn));
            hreg = (1.f - z) * n + z * hreg;
            int i = 32 * rank + gj;
            out[(((size_t)(b_base + gbb)) * SLEN + s) * E + i] = hreg;
            u64 h2 = f2x2(hreg, hreg);
            sm->hdup[i * 8 + gbb] = h2;  // own rank local
            uint32_t ah = s2u(&sm->hdup[i * 8 + gbb]);
#pragma unroll
            for (uint32_t rr = 0; rr < CLU; rr++)
                if (rr != rank) stc64(ah, rr, h2);
        }
        carrive();
        prefw<4>((const ulonglong2*)g_WA, lane, warp, rank, pA0, pA1, pA2, pA3);
        cwait();
    }
}

extern "C" void kernel_launch(void* const* d_in, const int* in_sizes, int n_in,
                              void* d_out, int out_size) {
    const float* sig = (const float*)d_in[0];
    const float* bases = (const float*)d_in[1];
    const uint32_t* mask = (const uint32_t*)d_in[2];
    const float* Ww = (const float*)d_in[3];
    const float* Wb = (const float*)d_in[4];
    const float* lng = (const float*)d_in[5];
    const float* lnb = (const float*)d_in[6];
    const float* wih = (const float*)d_in[7];
    const float* bihp = (const float*)d_in[8];
    const float* whh = (const float*)d_in[9];
    const float* bhhp = (const float*)d_in[10];
    const float* h0 = (const float*)d_in[11];
    float* out = (float*)d_out;

    cudaFuncSetAttribute(gru, cudaFuncAttributeMaxDynamicSharedMemorySize,
                         (int)sizeof(SM));
    prep<<<3072, 256>>>(Ww, wih, whh);
    gru<<<NB, NTHR, sizeof(SM)>>>(sig, bases, mask, Wb, lng, lnb, bihp, bhhp, h0, out);
}

// round 8
// speedup vs baseline: 2.0247x; 2.0247x over previous
#include <cuda_runtime.h>
#include <cstdint>

#define E 256
#define SLEN 64
#define TLEN 512
#define CLU 8
#define NTHR 256
#define BPC 4

typedef unsigned long long u64;

// WA: [k=256][1024 cols]. Rank r owns cols [128r,128r+128):
//   c<32: W_w row (32r+c) (v, scattered to batch-owner CTA pair)
//   c>=32: cc=c-32=3j+g: w_hh row (g*256+32r+j) (gh triplets, local)
// WX: [k=512][1024]: c<96: 3j+g -> w_ih row (g*256+32r+j); else zero pad.
__device__ float4 g_WA[256 * 256];
__device__ float4 g_WX[512 * 256];

__global__ void prep(const float* __restrict__ Ww, const float* __restrict__ wih,
                     const float* __restrict__ whh) {
    int idx = blockIdx.x * blockDim.x + threadIdx.x;
    float* WA = (float*)g_WA;
    float* WX = (float*)g_WX;
    if (idx < 256 * 1024) {
        int k = idx >> 10, cg = idx & 1023, r = cg >> 7, c = cg & 127;
        if (c < 32) WA[idx] = Ww[(32 * r + c) * 256 + k];
        else {
            int cc = c - 32, j = cc / 3, g = cc - 3 * j;
            WA[idx] = whh[(g * 256 + 32 * r + j) * 256 + k];
        }
    }
    int idx2 = idx - 256 * 1024;
    if (idx2 >= 0 && idx2 < 512 * 1024) {
        int k = idx2 >> 10, cg = idx2 & 1023, r = cg >> 7, c = cg & 127;
        if (c < 96) {
            int j = c / 3, g = c - 3 * j;
            WX[idx2] = wih[(g * 256 + 32 * r + j) * 512 + k];
        } else WX[idx2] = 0.f;
    }
}

// ---------------- helpers ----------------------------------------------------
__device__ __forceinline__ u64 f2x2(float a, float b) {
    u64 r; asm("mov.b64 %0,{%1,%2};" : "=l"(r) : "f"(a), "f"(b)); return r;
}
__device__ __forceinline__ void unpk(u64 v, float& a, float& b) {
    asm("mov.b64 {%0,%1},%2;" : "=f"(a), "=f"(b) : "l"(v));
}
__device__ __forceinline__ u64 fma2(u64 a, u64 b, u64 c) {
    u64 d; asm("fma.rn.f32x2 %0,%1,%2,%3;" : "=l"(d) : "l"(a), "l"(b), "l"(c)); return d;
}
__device__ __forceinline__ u64 mul2(u64 a, u64 b) {
    u64 d; asm("mul.rn.f32x2 %0,%1,%2;" : "=l"(d) : "l"(a), "l"(b)); return d;
}
__device__ __forceinline__ u64 add2(u64 a, u64 b) {
    u64 d; asm("add.rn.f32x2 %0,%1,%2;" : "=l"(d) : "l"(a), "l"(b)); return d;
}
__device__ __forceinline__ uint32_t s2u(const void* p) {
    return (uint32_t)__cvta_generic_to_shared(p);
}
__device__ __forceinline__ void stc64(uint32_t a, uint32_t rk, u64 v) {
    uint32_t ra;
    asm volatile("mapa.shared::cluster.u32 %0,%1,%2;" : "=r"(ra) : "r"(a), "r"(rk));
    asm volatile("st.shared::cluster.u64 [%0],%1;" ::"r"(ra), "l"(v) : "memory");
}
__device__ __forceinline__ void stc32(uint32_t a, uint32_t rk, float v) {
    uint32_t ra;
    asm volatile("mapa.shared::cluster.u32 %0,%1,%2;" : "=r"(ra) : "r"(a), "r"(rk));
    asm volatile("st.shared::cluster.f32 [%0],%1;" ::"r"(ra), "f"(v) : "memory");
}
__device__ __forceinline__ void csync() {
    asm volatile("barrier.cluster.arrive.aligned;" ::: "memory");
    asm volatile("barrier.cluster.wait.aligned;" ::: "memory");
}

struct __align__(16) SM {
    u64 hdup[256 * BPC];    // (h,h) per [k][bb]            8 KB
    u64 lndup[512 * BPC];   // (y,y) per [k][bb]           16 KB
    float part[8 * 514];    // matvec partials / ctx scratch 16.4 KB
    float v_own[E];
    float ctx_s[E];         // own-half unnormalized ctx
    float ctx_p[E];         // partner-half ctx (received)
    float gh_loc[BPC * 96];
    float gx_loc[BPC * 96];
    uint32_t msk[256];      // own T-half mask
    float2 mS[8];
    float wgtS[8];
    float2 mcS;             // own combined (m, S)
    float2 mSp;             // partner's (m, S)
    float redA[12];
    float redB[12];
};

// 128-col slice (this rank) x 4 batches; warp = k-partition of NT*4.
template <int NT>
__device__ __forceinline__ void matslice2(const ulonglong2* __restrict__ Wq,
                                          const ulonglong2* __restrict__ hq,
                                          float* part, int lane, int warp, int rank) {
    u64 acc[2][4];
#pragma unroll
    for (int p = 0; p < 2; p++)
#pragma unroll
        for (int b = 0; b < 4; b++) acc[p][b] = 0ull;
    const ulonglong2* wp = Wq + (size_t)(warp * NT * 4) * 256 + rank * 32 + lane;
    const ulonglong2* hp = hq + (warp * NT * 4) * 2;
#pragma unroll 2
    for (int t = 0; t < NT; t++) {
        ulonglong2 w0 = wp[0], w1 = wp[256], w2 = wp[512], w3 = wp[768];
        wp += 1024;
        ulonglong2 h0a = hp[0], h0b = hp[1], h1a = hp[2], h1b = hp[3];
        ulonglong2 h2a = hp[4], h2b = hp[5], h3a = hp[6], h3b = hp[7];
        hp += 8;
        acc[0][0] = fma2(w0.x, h0a.x, acc[0][0]); acc[1][0] = fma2(w0.y, h0a.x, acc[1][0]);
        acc[0][1] = fma2(w0.x, h0a.y, acc[0][1]); acc[1][1] = fma2(w0.y, h0a.y, acc[1][1]);
        acc[0][2] = fma2(w0.x, h0b.x, acc[0][2]); acc[1][2] = fma2(w0.y, h0b.x, acc[1][2]);
        acc[0][3] = fma2(w0.x, h0b.y, acc[0][3]); acc[1][3] = fma2(w0.y, h0b.y, acc[1][3]);
        acc[0][0] = fma2(w1.x, h1a.x, acc[0][0]); acc[1][0] = fma2(w1.y, h1a.x, acc[1][0]);
        acc[0][1] = fma2(w1.x, h1a.y, acc[0][1]); acc[1][1] = fma2(w1.y, h1a.y, acc[1][1]);
        acc[0][2] = fma2(w1.x, h1b.x, acc[0][2]); acc[1][2] = fma2(w1.y, h1b.x, acc[1][2]);
        acc[0][3] = fma2(w1.x, h1b.y, acc[0][3]); acc[1][3] = fma2(w1.y, h1b.y, acc[1][3]);
        acc[0][0] = fma2(w2.x, h2a.x, acc[0][0]); acc[1][0] = fma2(w2.y, h2a.x, acc[1][0]);
        acc[0][1] = fma2(w2.x, h2a.y, acc[0][1]); acc[1][1] = fma2(w2.y, h2a.y, acc[1][1]);
        acc[0][2] = fma2(w2.x, h2b.x, acc[0][2]); acc[1][2] = fma2(w2.y, h2b.x, acc[1][2]);
        acc[0][3] = fma2(w2.x, h2b.y, acc[0][3]); acc[1][3] = fma2(w2.y, h2b.y, acc[1][3]);
        acc[0][0] = fma2(w3.x, h3a.x, acc[0][0]); acc[1][0] = fma2(w3.y, h3a.x, acc[1][0]);
        acc[0][1] = fma2(w3.x, h3a.y, acc[0][1]); acc[1][1] = fma2(w3.y, h3a.y, acc[1][1]);
        acc[0][2] = fma2(w3.x, h3b.x, acc[0][2]); acc[1][2] = fma2(w3.y, h3b.x, acc[1][2]);
        acc[0][3] = fma2(w3.x, h3b.y, acc[0][3]); acc[1][3] = fma2(w3.y, h3b.y, acc[1][3]);
    }
#pragma unroll
    for (int p = 0; p < 2; p++)
#pragma unroll
        for (int b = 0; b < 4; b++) {
            int x = b * 128 + 4 * lane + 2 * p;
            *(u64*)(part + warp * 514 + x) = acc[p][b];
        }
}

__device__ __forceinline__ void mat_reduce(SM* sm, int tid, int rank, int phase) {
    int x = 2 * tid;  // [0,512): 4 batches x 128 cols
    u64 s = 0ull;
#pragma unroll
    for (int w = 0; w < 8; w++) s = add2(s, *(const u64*)(sm->part + w * 514 + x));
    int b = x >> 7, c = x & 127;
    if (phase == 0) {
        if (c < 32) {  // v row 32*rank+c of batch b -> both CTAs of the pair
            uint32_t a = s2u(&sm->v_own[32 * rank + c]);
            stc64(a, (uint32_t)(2 * b), s);
            stc64(a, (uint32_t)(2 * b + 1), s);
        } else *(u64*)(&sm->gh_loc[b * 96 + (c - 32)]) = s;
    } else {
        if (c < 96) *(u64*)(&sm->gx_loc[b * 96 + c]) = s;
    }
}

__global__ void __cluster_dims__(CLU, 1, 1) __launch_bounds__(NTHR, 2)
gru(const float* __restrict__ sig, const float* __restrict__ bases,
    const uint32_t* __restrict__ mask, const float* __restrict__ Wb,
    const float* __restrict__ lng, const float* __restrict__ lnb,
    const float* __restrict__ bih, const float* __restrict__ bhh,
    const float* __restrict__ h0, float* __restrict__ out) {
    extern __shared__ char smraw[];
    SM* sm = (SM*)smraw;
    const int tid = threadIdx.x, lane = tid & 31, warp = tid >> 5;
    uint32_t rank;
    asm("mov.u32 %0,%%cluster_ctarank;" : "=r"(rank));
    const int b_base = (blockIdx.x >> 3) * BPC;
    const int b = b_base + (int)(rank >> 1);      // attention batch of this CTA
    const int toff = (rank & 1) * 256;            // own T-half
    const float NEGINF = __int_as_float(0xff800000);

    // per-thread constants
    float bihr = 0.f, bihz = 0.f, bihn = 0.f;
    float bhhr = 0.f, bhhz = 0.f, bhhn = 0.f, hreg = 0.f;
    const int gj = tid & 31, gbb = tid >> 5;  // gates mapping for tid<128
    if (tid < 128) {
        int i = 32 * rank + gj;
        bihr = bih[i]; bihz = bih[256 + i]; bihn = bih[512 + i];
        bhhr = bhh[i]; bhhz = bhh[256 + i]; bhhn = bhh[512 + i];
        hreg = h0[i];
    }
    {
        float hv = h0[tid];
#pragma unroll
        for (int bb = 0; bb < BPC; bb++) sm->hdup[tid * BPC + bb] = f2x2(hv, hv);
    }
    const int lnidx = toff + tid;  // this CTA's LN half
    const float lngr = lng[lnidx], lnbr = lnb[lnidx];
    const ulonglong2 wbA = ((const ulonglong2*)Wb)[2 * lane];
    const ulonglong2 wbB = ((const ulonglong2*)Wb)[2 * lane + 1];
    sm->msk[tid] = mask[(size_t)b * TLEN + toff + tid];
    __syncthreads();
    csync();

    const ulonglong2* sq = (const ulonglong2*)(sig + (size_t)b * TLEN * E);

    for (int s = 0; s < SLEN; s++) {
        float xbase = bases[((size_t)b * SLEN + s) * E + tid];

        // ===== Phase A: v (to batch-owner pair) + gh (local), 4 batches =====
        matslice2<8>((const ulonglong2*)g_WA, (const ulonglong2*)sm->hdup,
                     sm->part, lane, warp, rank);
        __syncthreads();
        mat_reduce(sm, tid, rank, 0);
        csync();

        // ===== Attention: own batch, own 256-row T-half, 32 rows/warp =======
        ulonglong2 vr0 = ((const ulonglong2*)sm->v_own)[2 * lane];
        ulonglong2 vr1 = ((const ulonglong2*)sm->v_own)[2 * lane + 1];
        ulonglong2 va, vb;
        va.x = add2(vr0.x, wbA.x); va.y = add2(vr0.y, wbA.y);
        vb.x = add2(vr1.x, wbB.x); vb.y = add2(vr1.y, wbB.y);
        float mrun = -1e30f, Ss = 0.f;
        u64 c0 = 0, c1 = 0, c2 = 0, c3 = 0;
#pragma unroll 2
        for (int g = 0; g < 8; g++) {
            int tl = warp * 32 + g * 4;          // local row
            size_t tg = (size_t)(toff + tl) * 64;
            ulonglong2 r0a = sq[tg + 2 * lane],       r0b = sq[tg + 2 * lane + 1];
            ulonglong2 r1a = sq[tg + 64 + 2 * lane],  r1b = sq[tg + 64 + 2 * lane + 1];
            ulonglong2 r2a = sq[tg + 128 + 2 * lane], r2b = sq[tg + 128 + 2 * lane + 1];
            ulonglong2 r3a = sq[tg + 192 + 2 * lane], r3b = sq[tg + 192 + 2 * lane + 1];
            auto dotp = [&](ulonglong2 ra, ulonglong2 rb) {
                u64 a = mul2(ra.x, va.x);
                a = fma2(ra.y, va.y, a);
                a = fma2(rb.x, vb.x, a);
                a = fma2(rb.y, vb.y, a);
                float lo, hi; unpk(a, lo, hi);
                return lo + hi;
            };
            float a0 = dotp(r0a, r0b), a1 = dotp(r1a, r1b);
            float a2 = dotp(r2a, r2b), a3 = dotp(r3a, r3b);
#pragma unroll
            for (int o = 16; o; o >>= 1) {
                a0 += __shfl_xor_sync(0xffffffffu, a0, o);
                a1 += __shfl_xor_sync(0xffffffffu, a1, o);
                a2 += __shfl_xor_sync(0xffffffffu, a2, o);
                a3 += __shfl_xor_sync(0xffffffffu, a3, o);
            }
            if (sm->msk[tl + 0]) a0 = NEGINF;
            if (sm->msk[tl + 1]) a1 = NEGINF;
            if (sm->msk[tl + 2]) a2 = NEGINF;
            if (sm->msk[tl + 3]) a3 = NEGINF;
            float mg = fmaxf(fmaxf(a0, a1), fmaxf(a2, a3));
            if (mg > mrun) {
                float sc = __expf(mrun - mg);
                mrun = mg; Ss *= sc;
                u64 sc2 = f2x2(sc, sc);
                c0 = mul2(c0, sc2); c1 = mul2(c1, sc2);
                c2 = mul2(c2, sc2); c3 = mul2(c3, sc2);
            }
            float p0 = __expf(a0 - mrun), p1 = __expf(a1 - mrun);
            float p2 = __expf(a2 - mrun), p3 = __expf(a3 - mrun);
            Ss += (p0 + p1) + (p2 + p3);
            u64 q0 = f2x2(p0, p0), q1 = f2x2(p1, p1), q2 = f2x2(p2, p2), q3 = f2x2(p3, p3);
            c0 = fma2(q0, r0a.x, c0); c1 = fma2(q0, r0a.y, c1);
            c2 = fma2(q0, r0b.x, c2); c3 = fma2(q0, r0b.y, c3);
            c0 = fma2(q1, r1a.x, c0); c1 = fma2(q1, r1a.y, c1);
            c2 = fma2(q1, r1b.x, c2); c3 = fma2(q1, r1b.y, c3);
            c0 = fma2(q2, r2a.x, c0); c1 = fma2(q2, r2a.y, c1);
            c2 = fma2(q2, r2b.x, c2); c3 = fma2(q2, r2b.y, c3);
            c0 = fma2(q3, r3a.x, c0); c1 = fma2(q3, r3a.y, c1);
            c2 = fma2(q3, r3b.x, c2); c3 = fma2(q3, r3b.y, c3);
        }
        {
            u64* cw = (u64*)sm->part + warp * 132 + lane * 4;
            cw[0] = c0; cw[1] = c1; cw[2] = c2; cw[3] = c3;
            if (lane == 0) sm->mS[warp] = make_float2(mrun, Ss);
        }
        __syncthreads();
        if (tid < 32) {
            float mw = (lane < 8) ? sm->mS[lane].x : NEGINF;
            float Sw = (lane < 8) ? sm->mS[lane].y : 0.f;
            float m = mw;
#pragma unroll
            for (int o = 16; o; o >>= 1) m = fmaxf(m, __shfl_xor_sync(0xffffffffu, m, o));
            float wgt = __expf(mw - m);
            float Sc = Sw * wgt;
#pragma unroll
            for (int o = 16; o; o >>= 1) Sc += __shfl_xor_sync(0xffffffffu, Sc, o);
            if (lane < 8) sm->wgtS[lane] = wgt;
            if (lane == 0) sm->mcS = make_float2(m, Sc);
        }
        __syncthreads();
        {
            float acc = 0.f;
#pragma unroll
            for (int w = 0; w < 8; w++) acc += sm->part[w * 264 + tid] * sm->wgtS[w];
            sm->ctx_s[tid] = acc;
            stc32(s2u(&sm->ctx_p[tid]), rank ^ 1u, acc);  // send half to partner
            if (tid == 0) {
                float2 ms = sm->mcS;
                stc64(s2u(&sm->mSp), rank ^ 1u, f2x2(ms.x, ms.y));
            }
        }
        csync();

        // ===== Merge halves + LayerNorm + broadcast y-half to cluster =======
        {
            float2 mo = sm->mcS, mp = sm->mSp;
            float m = fmaxf(mo.x, mp.x);
            float w0 = __expf(mo.x - m), w1 = __expf(mp.x - m);
            float S = mo.y * w0 + mp.y * w1;
            float ctx = (sm->ctx_s[tid] * w0 + sm->ctx_p[tid] * w1) / S;
            float s1 = xbase + ctx, s2 = xbase * xbase + ctx * ctx;
#pragma unroll
            for (int o = 16; o; o >>= 1) {
                s1 += __shfl_xor_sync(0xffffffffu, s1, o);
                s2 += __shfl_xor_sync(0xffffffffu, s2, o);
            }
            if (lane == 0) { sm->redA[warp] = s1; sm->redB[warp] = s2; }
            __syncthreads();
            if (tid < 32) {
                float x1 = (lane < 8) ? sm->redA[lane] : 0.f;
                float x2 = (lane < 8) ? sm->redB[lane] : 0.f;
#pragma unroll
                for (int o = 16; o; o >>= 1) {
                    x1 += __shfl_xor_sync(0xffffffffu, x1, o);
                    x2 += __shfl_xor_sync(0xffffffffu, x2, o);
                }
                if (lane == 0) { sm->redA[8] = x1; sm->redB[8] = x2; }
            }
            __syncthreads();
            float mu = sm->redA[8] * (1.f / 512.f);
            float var = sm->redB[8] * (1.f / 512.f) - mu * mu;
            float rstd = rsqrtf(var + 1e-5f);
            float xv = (rank & 1) ? ctx : xbase;  // even: x-half, odd: ctx-half
            float y = (xv - mu) * rstd * lngr + lnbr;
            u64 y2 = f2x2(y, y);
            uint32_t addr = s2u(&sm->lndup[(size_t)lnidx * BPC + (rank >> 1)]);
#pragma unroll
            for (uint32_t rr = 0; rr < CLU; rr++) stc64(addr, rr, y2);
        }
        csync();

        // ===== Phase C: gx (local triplets), 4 batches =======================
        matslice2<16>((const ulonglong2*)g_WX, (const ulonglong2*)sm->lndup,
                      sm->part, lane, warp, rank);
        __syncthreads();
        mat_reduce(sm, tid, rank, 1);
        __syncthreads();

        // ===== Gates for this rank's 32 h-indices x 4 batches ================
        if (tid < 128) {
            int base = gbb * 96 + 3 * gj;
            float gxr = sm->gx_loc[base], gxz = sm->gx_loc[base + 1], gxn = sm->gx_loc[base + 2];
            float ghr = sm->gh_loc[base], ghz = sm->gh_loc[base + 1], ghn = sm->gh_loc[base + 2];
            float r = 1.f / (1.f + __expf(-(gxr + bihr + ghr + bhhr)));
            float z = 1.f / (1.f + __expf(-(gxz + bihz + ghz + bhhz)));
            float n = tanhf(gxn + bihn + r * (ghn + bhhn));
            hreg = (1.f - z) * n + z * hreg;
            int i = 32 * rank + gj;
            out[(((size_t)(b_base + gbb)) * SLEN + s) * E + i] = hreg;
            u64 h2 = f2x2(hreg, hreg);
            uint32_t ah = s2u(&sm->hdup[i * BPC + gbb]);
#pragma unroll
            for (uint32_t rr = 0; rr < CLU; rr++) stc64(ah, rr, h2);
        }
        csync();
    }
}

extern "C" void kernel_launch(void* const* d_in, const int* in_sizes, int n_in,
                              void* d_out, int out_size) {
    const float* sig = (const float*)d_in[0];
    const float* bases = (const float*)d_in[1];
    const uint32_t* mask = (const uint32_t*)d_in[2];
    const float* Ww = (const float*)d_in[3];
    const float* Wb = (const float*)d_in[4];
    const float* lng = (const float*)d_in[5];
    const float* lnb = (const float*)d_in[6];
    const float* wih = (const float*)d_in[7];
    const float* bihp = (const float*)d_in[8];
    const float* whh = (const float*)d_in[9];
    const float* bhhp = (const float*)d_in[10];
    const float* h0 = (const float*)d_in[11];
    float* out = (float*)d_out;

    cudaFuncSetAttribute(gru, cudaFuncAttributeMaxDynamicSharedMemorySize,
                         (int)sizeof(SM));
    prep<<<3072, 256>>>(Ww, wih, whh);
    gru<<<256, NTHR, sizeof(SM)>>>(sig, bases, mask, Wb, lng, lnb, bihp, bhhp, h0, out);
}